// round 15
// baseline (speedup 1.0000x reference)
#include <cuda_runtime.h>
#include <cuda_fp16.h>
#include <cstdint>

#define BATCH   16
#define IN_CH   256
#define NTOK    1024
#define NHEAD   8
// SCALE * log2(e): softmax done in exp2 domain
#define QSCALE  0.18033688f

// Scratch
__device__ __align__(16) __half g_x[BATCH * IN_CH * NTOK];     // x in half
__device__ __align__(16) __half g_w[1536 * IN_CH];             // qkv_w half
__device__ __align__(16) __half g_pw[256 * 512];               // proj_w half
__device__ __align__(16) __half g_q[BATCH * NHEAD * NTOK * 64];
__device__ __align__(16) __half g_k[BATCH * NHEAD * NTOK * 64];
__device__ __align__(16) __half g_v[BATCH * NHEAD * NTOK * 64];
__device__ __align__(16) __half g_o[BATCH * NHEAD * NTOK * 64];

__device__ __forceinline__ unsigned f2h2(float lo, float hi) {
    unsigned r;
    asm("cvt.rn.f16x2.f32 %0, %1, %2;" : "=r"(r) : "f"(hi), "f"(lo));
    return r;
}
__device__ __forceinline__ float ex2(float x) {
    float r;
    asm("ex2.approx.f32 %0, %1;" : "=f"(r) : "f"(x));
    return r;
}
__device__ __forceinline__ unsigned ex2h2(unsigned x) {
    asm("ex2.approx.f16x2 %0, %0;" : "+r"(x));
    return x;
}
__device__ __forceinline__ uint32_t smem_u32(const void* p) {
    uint32_t a;
    asm("{ .reg .u64 t; cvta.to.shared.u64 t, %1; cvt.u32.u64 %0, t; }" : "=r"(a) : "l"(p));
    return a;
}
__device__ __forceinline__ void mma16(float* d, const unsigned* a, const unsigned* b) {
    asm volatile(
        "mma.sync.aligned.m16n8k16.row.col.f32.f16.f16.f32 "
        "{%0,%1,%2,%3}, {%4,%5,%6,%7}, {%8,%9}, {%0,%1,%2,%3};\n"
        : "+f"(d[0]), "+f"(d[1]), "+f"(d[2]), "+f"(d[3])
        : "r"(a[0]), "r"(a[1]), "r"(a[2]), "r"(a[3]), "r"(b[0]), "r"(b[1]));
}
#define LDSM4(r0, r1, r2, r3, addr) \
    asm volatile("ldmatrix.sync.aligned.m8n8.x4.shared.b16 {%0,%1,%2,%3}, [%4];" \
        : "=r"(r0), "=r"(r1), "=r"(r2), "=r"(r3) : "r"(addr))
#define LDSM4T(r0, r1, r2, r3, addr) \
    asm volatile("ldmatrix.sync.aligned.m8n8.x4.trans.shared.b16 {%0,%1,%2,%3}, [%4];" \
        : "=r"(r0), "=r"(r1), "=r"(r2), "=r"(r3) : "r"(addr))
#define CPA16(dst, src) \
    asm volatile("cp.async.cg.shared.global [%0], [%1], 16;" :: "r"(dst), "l"(src))
#define CP_COMMIT() asm volatile("cp.async.commit_group;" ::: "memory")
#define CP_WAIT0()  asm volatile("cp.async.wait_group 0;" ::: "memory")
#define CP_WAIT1()  asm volatile("cp.async.wait_group 1;" ::: "memory")
#define CP_WAIT2()  asm volatile("cp.async.wait_group 2;" ::: "memory")

// ---------------------------------------------------------------------------
// Kernel 0: fp32 -> fp16 pre-convert (x, qkv_w, proj_w). One float4/thread.
// ---------------------------------------------------------------------------
#define X_F4   1048576            // 16*256*1024 / 4
#define W_F4   98304              // 1536*256 / 4
#define PW_F4  32768              // 256*512 / 4
__global__ void cvt_kernel(const float* __restrict__ x,
                           const float* __restrict__ w,
                           const float* __restrict__ pw)
{
    int i = blockIdx.x * 256 + threadIdx.x;
    const float4* src;
    __half* dst;
    int j;
    if (i < X_F4)            { src = (const float4*)x;  dst = g_x;  j = i; }
    else if (i < X_F4 + W_F4){ src = (const float4*)w;  dst = g_w;  j = i - X_F4; }
    else                     { src = (const float4*)pw; dst = g_pw; j = i - X_F4 - W_F4; }
    float4 v = src[j];
    *(uint2*)(dst + 4 * (size_t)j) = make_uint2(f2h2(v.x, v.y), f2h2(v.z, v.w));
}

// ---------------------------------------------------------------------------
// Kernel 1: QKV GEMM fp16. Block 128m x 128n, BK=32, 8 warps (2m x 4n),
// warp 64x32. 4-stage cp.async pipeline. (round-13 proven)
// ---------------------------------------------------------------------------
__global__ void __launch_bounds__(256, 2) qkv_gemm_kernel(
    const float* __restrict__ bias)
{
    extern __shared__ char smem[];
    const uint32_t sb = smem_u32(smem);
    const uint32_t Ab0 = sb;             // 4 x 32*272  = 34816
    const uint32_t Bb0 = sb + 34816;     // 4 x 128*80  = 40960

    const int b  = blockIdx.z;
    const int mT = blockIdx.x * 128;
    const int nT = blockIdx.y * 128;
    const int t = threadIdx.x, lane = t & 31, warp = t >> 5;
    const int wm = (warp & 1) * 64;
    const int wn = (warp >> 1) * 32;
    const int lr = lane >> 2, lc = lane & 3;
    const int l7 = lane & 7, l8 = (lane >> 3) & 1, l16 = lane >> 4;

    const __half* xb = g_x + (size_t)b * (IN_CH * NTOK);

    float acc[4][4][4];
#pragma unroll
    for (int i = 0; i < 4; i++)
#pragma unroll
        for (int j = 0; j < 4; j++)
#pragma unroll
            for (int q = 0; q < 4; q++) acc[i][j][q] = 0.f;

    const int a_k = t >> 3, a_c = t & 7;
    const int b_n = t >> 1, b_c = t & 1;
#define QKV_ISSUE(kk, buf) do { \
    uint32_t Ad = Ab0 + (buf) * 8704, Bd = Bb0 + (buf) * 10240; \
    _Pragma("unroll") \
    for (int i = 0; i < 2; i++) \
        CPA16(Ad + a_k * 272 + (a_c * 2 + i) * 16, \
              xb + (size_t)((kk) + a_k) * NTOK + mT + (a_c * 2 + i) * 8); \
    _Pragma("unroll") \
    for (int i = 0; i < 2; i++) \
        CPA16(Bd + b_n * 80 + (b_c * 2 + i) * 16, \
              g_w + (size_t)(nT + b_n) * IN_CH + (kk) + (b_c * 2 + i) * 8); \
    CP_COMMIT(); } while (0)

    const uint32_t aAl = (uint32_t)((l7 + 8 * l16) * 272 + 16 * l8 + wm * 2);
    const uint32_t aBl = (uint32_t)((wn + l7 + 8 * l16) * 80 + 16 * l8);

    QKV_ISSUE(0, 0);
    QKV_ISSUE(32, 1);
    QKV_ISSUE(64, 2);

#pragma unroll
    for (int it = 0; it < 8; it++) {
        const int buf = it & 3;
        CP_WAIT2();
        __syncthreads();
        if (it < 5) QKV_ISSUE((it + 3) * 32, (it + 3) & 3); else CP_COMMIT();
        const uint32_t Ac = Ab0 + buf * 8704 + aAl;
        const uint32_t Bc = Bb0 + buf * 10240 + aBl;
#pragma unroll
        for (int kg = 0; kg < 2; kg++) {
            unsigned a[4][4], bb[4][2];
#pragma unroll
            for (int mi = 0; mi < 4; mi++)
                LDSM4T(a[mi][0], a[mi][1], a[mi][2], a[mi][3],
                       Ac + kg * 4352 + mi * 32);
#pragma unroll
            for (int ntp = 0; ntp < 2; ntp++)
                LDSM4(bb[2 * ntp][0], bb[2 * ntp][1], bb[2 * ntp + 1][0], bb[2 * ntp + 1][1],
                      Bc + ntp * 1280 + kg * 32);
#pragma unroll
            for (int mi = 0; mi < 4; mi++)
#pragma unroll
                for (int ni = 0; ni < 4; ni++)
                    mma16(acc[mi][ni], a[mi], bb[ni]);
        }
    }

    // epilogue -> half g_q/g_k/g_v [b,h,tok,d]; q pre-scaled by SCALE*log2e
#pragma unroll
    for (int ni = 0; ni < 4; ni++) {
        int o = nT + wn + ni * 8 + 2 * lc;
        __half* dst;
        float sc = 1.f;
        if (o < 512)       { dst = g_q; sc = QSCALE; }
        else if (o < 1024) { dst = g_k; }
        else               { dst = g_v; }
        int head = (o >> 6) & 7, d = o & 63;
        float b0 = bias[o], b1 = bias[o + 1];
        __half* base = dst + ((size_t)(b * NHEAD + head) * NTOK) * 64 + d;
#pragma unroll
        for (int mi = 0; mi < 4; mi++) {
            int r = mT + wm + mi * 16 + lr;
            *(unsigned*)(base + (size_t)r * 64) =
                f2h2((acc[mi][ni][0] + b0) * sc, (acc[mi][ni][1] + b1) * sc);
            *(unsigned*)(base + (size_t)(r + 8) * 64) =
                f2h2((acc[mi][ni][2] + b0) * sc, (acc[mi][ni][3] + b1) * sc);
        }
    }
}

// ---------------------------------------------------------------------------
// Kernel 2: causal flash attention fp16, FA2 register softmax + ldmatrix.
// BM=128, BN=64, pair-processed key tiles; conditional rescale.
// (round-14 proven version, unchanged)
// ---------------------------------------------------------------------------
__global__ void __launch_bounds__(256, 2) attn_kernel()
{
    extern __shared__ char smem[];
    const uint32_t sb = smem_u32(smem);
    const uint32_t QPb = sb;             // [128][144B] = 18432 (Q staging)
    const uint32_t Kb0 = sb + 18432;     // 2 x [128][144B] = 36864
    const uint32_t Vb0 = sb + 55296;     // 2 x [128][144B] = 36864

    const int t = threadIdx.x, lane = t & 31, w = t >> 5;
    const int lr = lane >> 2, lc = lane & 3;
    const int l7 = lane & 7, l8 = (lane >> 3) & 1, l16 = lane >> 4;
    const int qt = 7 - blockIdx.x;       // heavy blocks first
    const int h = blockIdx.y, b = blockIdx.z;

    const size_t base = (size_t)(b * NHEAD + h) * (NTOK * 64);
    const __half* Qg = g_q + base + (size_t)qt * 128 * 64;
    const __half* Kg = g_k + base;
    const __half* Vg = g_v + base;

    const int r8 = t >> 3, c8 = t & 7;

#define KV2_ISSUE(p2, buf) do { \
    const __half* kg2 = Kg + (size_t)(p2) * 128 * 64; \
    const __half* vg2 = Vg + (size_t)(p2) * 128 * 64; \
    uint32_t Kn = Kb0 + (buf) * 18432, Vn = Vb0 + (buf) * 18432; \
    _Pragma("unroll") \
    for (int i = 0; i < 4; i++) \
        CPA16(Kn + (r8 + 32 * i) * 144 + c8 * 16, kg2 + (size_t)(r8 + 32 * i) * 64 + c8 * 8); \
    _Pragma("unroll") \
    for (int i = 0; i < 4; i++) \
        CPA16(Vn + (r8 + 32 * i) * 144 + c8 * 16, vg2 + (size_t)(r8 + 32 * i) * 64 + c8 * 8); \
    CP_COMMIT(); } while (0)

    // prologue: group0 = Q + pair0; group1 = pair1 (if any)
#pragma unroll
    for (int i = 0; i < 4; i++)
        CPA16(QPb + (r8 + 32 * i) * 144 + c8 * 16, Qg + (size_t)(r8 + 32 * i) * 64 + c8 * 8);
    KV2_ISSUE(0, 0);
    if (qt >= 1) { KV2_ISSUE(1, 1); CP_WAIT1(); } else { CP_WAIT0(); }
    __syncthreads();

    const uint32_t aQ = QPb + (16 * w + l7 + 8 * l8) * 144 + 16 * l16;
    const uint32_t aK = (uint32_t)((l7 + 8 * l16) * 144 + 16 * l8);
    const uint32_t aV = (uint32_t)((l7 + 8 * l8) * 144 + 16 * l16);

    unsigned qf[4][4];
#pragma unroll
    for (int g = 0; g < 4; g++)
        LDSM4(qf[g][0], qf[g][1], qf[g][2], qf[g][3], aQ + g * 32);

    const int row0 = 16 * w + lr;
    const int row1 = row0 + 8;

    float m0 = -1e30f, m1 = -1e30f, l0 = 0.f, l1 = 0.f;
    float oacc[8][4];
#pragma unroll
    for (int i = 0; i < 8; i++)
#pragma unroll
        for (int q = 0; q < 4; q++) oacc[i][q] = 0.f;

    const unsigned ONES2 = 0x3C003C00u;
    const unsigned onesb[2] = {ONES2, ONES2};

    for (int p = 0; p <= qt; p++) {
        const int buf = p & 1;

#pragma unroll
        for (int half = 0; half < 2; half++) {
            const uint32_t Kbase = Kb0 + buf * 18432 + half * 9216;
            const uint32_t Vbase = Vb0 + buf * 18432 + half * 9216;
            const int kt = 2 * p + half;
            const int off = kt * 64 - qt * 128;
            const int lim = min(8, max(0, ((16 * w + 15 - off) >> 3) + 1));

            if (lim > 0) {
                float s[8][4];
#pragma unroll
                for (int nt = 0; nt < 8; nt++) {
                    s[nt][0] = 0.f; s[nt][1] = 0.f; s[nt][2] = 0.f; s[nt][3] = 0.f;
                }
                if (off < 0) {
#pragma unroll
                    for (int g = 0; g < 4; g++) {
                        unsigned bb[8][2];
#pragma unroll
                        for (int ntp = 0; ntp < 4; ntp++)
                            LDSM4(bb[2 * ntp][0], bb[2 * ntp][1], bb[2 * ntp + 1][0], bb[2 * ntp + 1][1],
                                  Kbase + aK + ntp * 2304 + g * 32);
#pragma unroll
                        for (int nt = 0; nt < 8; nt++)
                            mma16(s[nt], qf[g], bb[nt]);
                    }
                } else {
#pragma unroll
                    for (int g = 0; g < 4; g++) {
                        unsigned bb[8][2];
#pragma unroll
                        for (int ntp = 0; ntp < 4; ntp++)
                            if (2 * ntp < lim)
                                LDSM4(bb[2 * ntp][0], bb[2 * ntp][1], bb[2 * ntp + 1][0], bb[2 * ntp + 1][1],
                                      Kbase + aK + ntp * 2304 + g * 32);
#pragma unroll
                        for (int nt = 0; nt < 8; nt++)
                            if (nt < lim)
                                mma16(s[nt], qf[g], bb[nt]);
                    }
#pragma unroll
                    for (int nt = 0; nt < 8; nt++) {
                        if (nt >= lim) {
                            s[nt][0] = s[nt][1] = s[nt][2] = s[nt][3] = -1e30f;
                        } else {
                            int c0 = off + nt * 8 + 2 * lc;
                            if (c0 > row0)     s[nt][0] = -1e30f;
                            if (c0 + 1 > row0) s[nt][1] = -1e30f;
                            if (c0 > row1)     s[nt][2] = -1e30f;
                            if (c0 + 1 > row1) s[nt][3] = -1e30f;
                        }
                    }
                }

                float mx0 = -1e30f, mx1 = -1e30f;
#pragma unroll
                for (int nt = 0; nt < 8; nt++) {
                    mx0 = fmaxf(mx0, fmaxf(s[nt][0], s[nt][1]));
                    mx1 = fmaxf(mx1, fmaxf(s[nt][2], s[nt][3]));
                }
                mx0 = fmaxf(mx0, __shfl_xor_sync(0xffffffffu, mx0, 1));
                mx0 = fmaxf(mx0, __shfl_xor_sync(0xffffffffu, mx0, 2));
                mx1 = fmaxf(mx1, __shfl_xor_sync(0xffffffffu, mx1, 1));
                mx1 = fmaxf(mx1, __shfl_xor_sync(0xffffffffu, mx1, 2));
                float m0n = fmaxf(m0, mx0), m1n = fmaxf(m1, mx1);

                bool changed = (m0n != m0) || (m1n != m1);
                if (__any_sync(0xffffffffu, changed)) {
                    float a0 = ex2(m0 - m0n), a1 = ex2(m1 - m1n);
                    m0 = m0n; m1 = m1n;
                    l0 *= a0; l1 *= a1;
#pragma unroll
                    for (int nt = 0; nt < 8; nt++) {
                        oacc[nt][0] *= a0; oacc[nt][1] *= a0;
                        oacc[nt][2] *= a1; oacc[nt][3] *= a1;
                    }
                }

                unsigned pf[4][4];
#pragma unroll
                for (int nt = 0; nt < 8; nt++) {
                    unsigned plo = ex2h2(f2h2(s[nt][0] - m0n, s[nt][1] - m0n));
                    unsigned phi = ex2h2(f2h2(s[nt][2] - m1n, s[nt][3] - m1n));
                    if ((nt & 1) == 0) {
                        pf[nt >> 1][0] = plo;
                        pf[nt >> 1][1] = phi;
                    } else {
                        pf[nt >> 1][2] = plo;
                        pf[nt >> 1][3] = phi;
                    }
                }

                float lacc[4] = {0.f, 0.f, 0.f, 0.f};
#pragma unroll
                for (int g = 0; g < 4; g++) {
                    if (off < 0 || 2 * g < lim) {
                        mma16(lacc, pf[g], onesb);
                        unsigned bb[8][2];
#pragma unroll
                        for (int ntp = 0; ntp < 4; ntp++)
                            LDSM4T(bb[2 * ntp][0], bb[2 * ntp][1], bb[2 * ntp + 1][0], bb[2 * ntp + 1][1],
                                   Vbase + aV + g * 2304 + ntp * 32);
#pragma unroll
                        for (int nt = 0; nt < 8; nt++)
                            mma16(oacc[nt], pf[g], bb[nt]);
                    }
                }
                l0 += lacc[0];
                l1 += lacc[2];
            }
        }

        if (p < qt) {
            CP_WAIT0();
            __syncthreads();
            if (p + 2 <= qt) KV2_ISSUE(p + 2, buf);
        }
    }

    float li0 = 1.f / l0, li1 = 1.f / l1;
    __half* Og = g_o + base + (size_t)qt * 128 * 64;
#pragma unroll
    for (int nt = 0; nt < 8; nt++) {
        int c = nt * 8 + 2 * lc;
        *(unsigned*)(Og + (size_t)row0 * 64 + c) = f2h2(oacc[nt][0] * li0, oacc[nt][1] * li0);
        *(unsigned*)(Og + (size_t)row1 * 64 + c) = f2h2(oacc[nt][2] * li1, oacc[nt][3] * li1);
    }
}

// ---------------------------------------------------------------------------
// Kernel 3: proj GEMM fp16. Block 128m x 64n (grid 512 -> 1.7 waves),
// 8 warps as 4m x 2n (warp 32x32), BK=32, K=512, 3-stage cp.async.
// __launch_bounds__(256,3): ~80 regs -> 3 CTAs/SM (24 warps).
// K-order per output unchanged -> bit-identical results.
// ---------------------------------------------------------------------------
__global__ void __launch_bounds__(256, 3) proj_gemm_kernel(
    const float* __restrict__ pb, float* __restrict__ out)
{
    extern __shared__ char smem[];
    const uint32_t sb = smem_u32(smem);
    const uint32_t Ab0 = sb;             // 3 x 128*80 = 30720
    const uint32_t Bb0 = sb + 30720;     // 3 x 64*80  = 15360

    const int b  = blockIdx.z;
    const int mT = blockIdx.x * 128;
    const int nT = blockIdx.y * 64;
    const int t = threadIdx.x, lane = t & 31, warp = t >> 5;
    const int wm = (warp & 3) * 32;
    const int wn = (warp >> 2) * 32;
    const int lr = lane >> 2, lc = lane & 3;
    const int l7 = lane & 7, l8 = (lane >> 3) & 1, l16 = lane >> 4;

    const __half* ob = g_o + (size_t)b * (NHEAD * NTOK * 64);

    float acc[2][4][4];
#pragma unroll
    for (int i = 0; i < 2; i++)
#pragma unroll
        for (int j = 0; j < 4; j++)
#pragma unroll
            for (int q = 0; q < 4; q++) acc[i][j][q] = 0.f;

    const int a_r = t >> 1, a_c = t & 1;   // A: 128 rows, 2 threads/row, 2 cpa each
    const int b_r = t >> 2, b_c = t & 3;   // B: 64 rows, 4 threads/row, 1 cpa each
#define PROJ_ISSUE(kk, buf) do { \
    int head = (kk) >> 6, d0 = (kk) & 63; \
    const __half* src = ob + (size_t)head * (NTOK * 64); \
    uint32_t Ad = Ab0 + (buf) * 10240, Bd = Bb0 + (buf) * 5120; \
    _Pragma("unroll") \
    for (int i = 0; i < 2; i++) \
        CPA16(Ad + a_r * 80 + (a_c * 2 + i) * 16, \
              src + (size_t)(mT + a_r) * 64 + d0 + (a_c * 2 + i) * 8); \
    CPA16(Bd + b_r * 80 + b_c * 16, \
          g_pw + (size_t)(nT + b_r) * 512 + (kk) + b_c * 8); \
    CP_COMMIT(); } while (0)

    const uint32_t aAl = (uint32_t)((wm + l7 + 8 * l8) * 80 + 16 * l16);
    const uint32_t aBl = (uint32_t)((wn + l7 + 8 * l16) * 80 + 16 * l8);

    PROJ_ISSUE(0, 0);
    PROJ_ISSUE(32, 1);

#pragma unroll
    for (int it = 0; it < 16; it++) {
        const int buf = it % 3;
        CP_WAIT1();
        __syncthreads();
        if (it < 14) PROJ_ISSUE((it + 2) * 32, (it + 2) % 3); else CP_COMMIT();
        const uint32_t Ac = Ab0 + buf * 10240 + aAl;
        const uint32_t Bc = Bb0 + buf * 5120 + aBl;
#pragma unroll
        for (int kg = 0; kg < 2; kg++) {
            unsigned a[2][4], bb[4][2];
#pragma unroll
            for (int mi = 0; mi < 2; mi++)
                LDSM4(a[mi][0], a[mi][1], a[mi][2], a[mi][3],
                      Ac + mi * 1280 + kg * 32);
#pragma unroll
            for (int ntp = 0; ntp < 2; ntp++)
                LDSM4(bb[2 * ntp][0], bb[2 * ntp][1], bb[2 * ntp + 1][0], bb[2 * ntp + 1][1],
                      Bc + ntp * 1280 + kg * 32);
#pragma unroll
            for (int mi = 0; mi < 2; mi++)
#pragma unroll
                for (int ni = 0; ni < 4; ni++)
                    mma16(acc[mi][ni], a[mi], bb[ni]);
        }
    }
    __syncthreads();

    // transpose epilogue through smem: Cs[n(64)][m(128)] ld132 (float)
    float* Cs = (float*)smem;
#pragma unroll
    for (int ni = 0; ni < 4; ni++) {
        int n = wn + ni * 8 + 2 * lc;
#pragma unroll
        for (int mi = 0; mi < 2; mi++) {
            int m = wm + mi * 16 + lr;
            Cs[n * 132 + m]           = acc[mi][ni][0];
            Cs[(n + 1) * 132 + m]     = acc[mi][ni][1];
            Cs[n * 132 + m + 8]       = acc[mi][ni][2];
            Cs[(n + 1) * 132 + m + 8] = acc[mi][ni][3];
        }
    }
    __syncthreads();

#pragma unroll
    for (int i = 0; i < 8; i++) {
        int idx = t + i * 256;
        int n = idx >> 5, mq = (idx & 31) * 4;
        float bi = pb[nT + n];
        const float* src = &Cs[n * 132 + mq];
        float4 v;
        v.x = src[0] + bi; v.y = src[1] + bi; v.z = src[2] + bi; v.w = src[3] + bi;
        *(float4*)(out + (size_t)(b * 256 + nT + n) * NTOK + mT + mq) = v;
    }
}

// ---------------------------------------------------------------------------
extern "C" void kernel_launch(void* const* d_in, const int* in_sizes, int n_in,
                              void* d_out, int out_size)
{
    const float* x      = (const float*)d_in[0];
    const float* qkv_w  = (const float*)d_in[1];
    const float* qkv_b  = (const float*)d_in[2];
    const float* proj_w = (const float*)d_in[3];
    const float* proj_b = (const float*)d_in[4];
    float* out = (float*)d_out;

    const int qkv_smem  = 75776;
    const int attn_smem = 92160;
    const int proj_smem = 46080;   // mainloop 46080 > epilogue 64*132*4=33792
    cudaFuncSetAttribute(qkv_gemm_kernel, cudaFuncAttributeMaxDynamicSharedMemorySize, qkv_smem);
    cudaFuncSetAttribute(attn_kernel, cudaFuncAttributeMaxDynamicSharedMemorySize, attn_smem);
    cudaFuncSetAttribute(proj_gemm_kernel, cudaFuncAttributeMaxDynamicSharedMemorySize, proj_smem);

    cvt_kernel<<<(X_F4 + W_F4 + PW_F4) / 256, 256>>>(x, qkv_w, proj_w);
    qkv_gemm_kernel<<<dim3(8, 12, BATCH), 256, qkv_smem>>>(qkv_b);
    attn_kernel<<<dim3(8, NHEAD, BATCH), 256, attn_smem>>>();
    proj_gemm_kernel<<<dim3(8, 4, BATCH), 256, proj_smem>>>(proj_b, out);
}

// round 16
// speedup vs baseline: 1.0332x; 1.0332x over previous
#include <cuda_runtime.h>
#include <cuda_fp16.h>
#include <cstdint>

#define BATCH   16
#define IN_CH   256
#define NTOK    1024
#define NHEAD   8
// SCALE * log2(e): softmax done in exp2 domain
#define QSCALE  0.18033688f

// Scratch
__device__ __align__(16) __half g_x[BATCH * IN_CH * NTOK];     // x in half
__device__ __align__(16) __half g_w[1536 * IN_CH];             // qkv_w half
__device__ __align__(16) __half g_pw[256 * 512];               // proj_w half
__device__ __align__(16) __half g_q[BATCH * NHEAD * NTOK * 64];
__device__ __align__(16) __half g_k[BATCH * NHEAD * NTOK * 64];
__device__ __align__(16) __half g_v[BATCH * NHEAD * NTOK * 64];
__device__ __align__(16) __half g_o[BATCH * NHEAD * NTOK * 64];

__device__ __forceinline__ unsigned f2h2(float lo, float hi) {
    unsigned r;
    asm("cvt.rn.f16x2.f32 %0, %1, %2;" : "=r"(r) : "f"(hi), "f"(lo));
    return r;
}
__device__ __forceinline__ float ex2(float x) {
    float r;
    asm("ex2.approx.f32 %0, %1;" : "=f"(r) : "f"(x));
    return r;
}
__device__ __forceinline__ unsigned ex2h2(unsigned x) {
    asm("ex2.approx.f16x2 %0, %0;" : "+r"(x));
    return x;
}
__device__ __forceinline__ uint32_t smem_u32(const void* p) {
    uint32_t a;
    asm("{ .reg .u64 t; cvta.to.shared.u64 t, %1; cvt.u32.u64 %0, t; }" : "=r"(a) : "l"(p));
    return a;
}
__device__ __forceinline__ void mma16(float* d, const unsigned* a, const unsigned* b) {
    asm volatile(
        "mma.sync.aligned.m16n8k16.row.col.f32.f16.f16.f32 "
        "{%0,%1,%2,%3}, {%4,%5,%6,%7}, {%8,%9}, {%0,%1,%2,%3};\n"
        : "+f"(d[0]), "+f"(d[1]), "+f"(d[2]), "+f"(d[3])
        : "r"(a[0]), "r"(a[1]), "r"(a[2]), "r"(a[3]), "r"(b[0]), "r"(b[1]));
}
#define LDSM4(r0, r1, r2, r3, addr) \
    asm volatile("ldmatrix.sync.aligned.m8n8.x4.shared.b16 {%0,%1,%2,%3}, [%4];" \
        : "=r"(r0), "=r"(r1), "=r"(r2), "=r"(r3) : "r"(addr))
#define LDSM4T(r0, r1, r2, r3, addr) \
    asm volatile("ldmatrix.sync.aligned.m8n8.x4.trans.shared.b16 {%0,%1,%2,%3}, [%4];" \
        : "=r"(r0), "=r"(r1), "=r"(r2), "=r"(r3) : "r"(addr))
#define CPA16(dst, src) \
    asm volatile("cp.async.cg.shared.global [%0], [%1], 16;" :: "r"(dst), "l"(src))
#define CP_COMMIT() asm volatile("cp.async.commit_group;" ::: "memory")
#define CP_WAIT0()  asm volatile("cp.async.wait_group 0;" ::: "memory")
#define CP_WAIT1()  asm volatile("cp.async.wait_group 1;" ::: "memory")
#define CP_WAIT2()  asm volatile("cp.async.wait_group 2;" ::: "memory")

// ---------------------------------------------------------------------------
// Kernel 0: fp32 -> fp16 pre-convert (x, qkv_w, proj_w). One float4/thread.
// ---------------------------------------------------------------------------
#define X_F4   1048576            // 16*256*1024 / 4
#define W_F4   98304              // 1536*256 / 4
#define PW_F4  32768              // 256*512 / 4
__global__ void cvt_kernel(const float* __restrict__ x,
                           const float* __restrict__ w,
                           const float* __restrict__ pw)
{
    int i = blockIdx.x * 256 + threadIdx.x;
    const float4* src;
    __half* dst;
    int j;
    if (i < X_F4)            { src = (const float4*)x;  dst = g_x;  j = i; }
    else if (i < X_F4 + W_F4){ src = (const float4*)w;  dst = g_w;  j = i - X_F4; }
    else                     { src = (const float4*)pw; dst = g_pw; j = i - X_F4 - W_F4; }
    float4 v = src[j];
    *(uint2*)(dst + 4 * (size_t)j) = make_uint2(f2h2(v.x, v.y), f2h2(v.z, v.w));
}

// ---------------------------------------------------------------------------
// Kernel 1: QKV GEMM fp16. Block 128m x 128n, BK=32, 8 warps (2m x 4n),
// warp 64x32. 4-stage cp.async pipeline. (round-13 proven)
// ---------------------------------------------------------------------------
__global__ void __launch_bounds__(256, 2) qkv_gemm_kernel(
    const float* __restrict__ bias)
{
    extern __shared__ char smem[];
    const uint32_t sb = smem_u32(smem);
    const uint32_t Ab0 = sb;             // 4 x 32*272  = 34816
    const uint32_t Bb0 = sb + 34816;     // 4 x 128*80  = 40960

    const int b  = blockIdx.z;
    const int mT = blockIdx.x * 128;
    const int nT = blockIdx.y * 128;
    const int t = threadIdx.x, lane = t & 31, warp = t >> 5;
    const int wm = (warp & 1) * 64;
    const int wn = (warp >> 1) * 32;
    const int lr = lane >> 2, lc = lane & 3;
    const int l7 = lane & 7, l8 = (lane >> 3) & 1, l16 = lane >> 4;

    const __half* xb = g_x + (size_t)b * (IN_CH * NTOK);

    float acc[4][4][4];
#pragma unroll
    for (int i = 0; i < 4; i++)
#pragma unroll
        for (int j = 0; j < 4; j++)
#pragma unroll
            for (int q = 0; q < 4; q++) acc[i][j][q] = 0.f;

    const int a_k = t >> 3, a_c = t & 7;
    const int b_n = t >> 1, b_c = t & 1;
#define QKV_ISSUE(kk, buf) do { \
    uint32_t Ad = Ab0 + (buf) * 8704, Bd = Bb0 + (buf) * 10240; \
    _Pragma("unroll") \
    for (int i = 0; i < 2; i++) \
        CPA16(Ad + a_k * 272 + (a_c * 2 + i) * 16, \
              xb + (size_t)((kk) + a_k) * NTOK + mT + (a_c * 2 + i) * 8); \
    _Pragma("unroll") \
    for (int i = 0; i < 2; i++) \
        CPA16(Bd + b_n * 80 + (b_c * 2 + i) * 16, \
              g_w + (size_t)(nT + b_n) * IN_CH + (kk) + (b_c * 2 + i) * 8); \
    CP_COMMIT(); } while (0)

    const uint32_t aAl = (uint32_t)((l7 + 8 * l16) * 272 + 16 * l8 + wm * 2);
    const uint32_t aBl = (uint32_t)((wn + l7 + 8 * l16) * 80 + 16 * l8);

    QKV_ISSUE(0, 0);
    QKV_ISSUE(32, 1);
    QKV_ISSUE(64, 2);

#pragma unroll
    for (int it = 0; it < 8; it++) {
        const int buf = it & 3;
        CP_WAIT2();
        __syncthreads();
        if (it < 5) QKV_ISSUE((it + 3) * 32, (it + 3) & 3); else CP_COMMIT();
        const uint32_t Ac = Ab0 + buf * 8704 + aAl;
        const uint32_t Bc = Bb0 + buf * 10240 + aBl;
#pragma unroll
        for (int kg = 0; kg < 2; kg++) {
            unsigned a[4][4], bb[4][2];
#pragma unroll
            for (int mi = 0; mi < 4; mi++)
                LDSM4T(a[mi][0], a[mi][1], a[mi][2], a[mi][3],
                       Ac + kg * 4352 + mi * 32);
#pragma unroll
            for (int ntp = 0; ntp < 2; ntp++)
                LDSM4(bb[2 * ntp][0], bb[2 * ntp][1], bb[2 * ntp + 1][0], bb[2 * ntp + 1][1],
                      Bc + ntp * 1280 + kg * 32);
#pragma unroll
            for (int mi = 0; mi < 4; mi++)
#pragma unroll
                for (int ni = 0; ni < 4; ni++)
                    mma16(acc[mi][ni], a[mi], bb[ni]);
        }
    }

    // epilogue -> half g_q/g_k/g_v [b,h,tok,d]; q pre-scaled by SCALE*log2e
#pragma unroll
    for (int ni = 0; ni < 4; ni++) {
        int o = nT + wn + ni * 8 + 2 * lc;
        __half* dst;
        float sc = 1.f;
        if (o < 512)       { dst = g_q; sc = QSCALE; }
        else if (o < 1024) { dst = g_k; }
        else               { dst = g_v; }
        int head = (o >> 6) & 7, d = o & 63;
        float b0 = bias[o], b1 = bias[o + 1];
        __half* base = dst + ((size_t)(b * NHEAD + head) * NTOK) * 64 + d;
#pragma unroll
        for (int mi = 0; mi < 4; mi++) {
            int r = mT + wm + mi * 16 + lr;
            *(unsigned*)(base + (size_t)r * 64) =
                f2h2((acc[mi][ni][0] + b0) * sc, (acc[mi][ni][1] + b1) * sc);
            *(unsigned*)(base + (size_t)(r + 8) * 64) =
                f2h2((acc[mi][ni][2] + b0) * sc, (acc[mi][ni][3] + b1) * sc);
        }
    }
}

// ---------------------------------------------------------------------------
// Kernel 2: causal flash attention fp16, FA2 register softmax + ldmatrix.
// BM=128, BN=64, pair-processed key tiles; conditional rescale.
// LOAD-BALANCED: each block processes TWO q-tiles, qt = 7-bx then bx,
// so every block does exactly 18 tile-units (uniform jobs, grid 4x8x16).
// ---------------------------------------------------------------------------
__global__ void __launch_bounds__(256, 2) attn_kernel()
{
    extern __shared__ char smem[];
    const uint32_t sb = smem_u32(smem);
    const uint32_t QPb = sb;             // [128][144B] = 18432 (Q staging)
    const uint32_t Kb0 = sb + 18432;     // 2 x [128][144B] = 36864
    const uint32_t Vb0 = sb + 55296;     // 2 x [128][144B] = 36864

    const int t = threadIdx.x, lane = t & 31, w = t >> 5;
    const int lr = lane >> 2, lc = lane & 3;
    const int l7 = lane & 7, l8 = (lane >> 3) & 1, l16 = lane >> 4;
    const int bx = blockIdx.x;           // 0..3
    const int h = blockIdx.y, b = blockIdx.z;

    const size_t base = (size_t)(b * NHEAD + h) * (NTOK * 64);
    const __half* Kg = g_k + base;
    const __half* Vg = g_v + base;

    const int r8 = t >> 3, c8 = t & 7;

#define KV2_ISSUE(p2, buf) do { \
    const __half* kg2 = Kg + (size_t)(p2) * 128 * 64; \
    const __half* vg2 = Vg + (size_t)(p2) * 128 * 64; \
    uint32_t Kn = Kb0 + (buf) * 18432, Vn = Vb0 + (buf) * 18432; \
    _Pragma("unroll") \
    for (int i = 0; i < 4; i++) \
        CPA16(Kn + (r8 + 32 * i) * 144 + c8 * 16, kg2 + (size_t)(r8 + 32 * i) * 64 + c8 * 8); \
    _Pragma("unroll") \
    for (int i = 0; i < 4; i++) \
        CPA16(Vn + (r8 + 32 * i) * 144 + c8 * 16, vg2 + (size_t)(r8 + 32 * i) * 64 + c8 * 8); \
    CP_COMMIT(); } while (0)

    // fragment lane-addresses (bytes), qt-independent
    const uint32_t aQ = QPb + (16 * w + l7 + 8 * l8) * 144 + 16 * l16;
    const uint32_t aK = (uint32_t)((l7 + 8 * l16) * 144 + 16 * l8);
    const uint32_t aV = (uint32_t)((l7 + 8 * l8) * 144 + 16 * l16);

    const int row0 = 16 * w + lr;
    const int row1 = row0 + 8;

    const unsigned ONES2 = 0x3C003C00u;
    const unsigned onesb[2] = {ONES2, ONES2};

    for (int sub = 0; sub < 2; sub++) {
        const int qt = sub ? bx : 7 - bx;   // heavy sub-problem first
        if (sub) __syncthreads();           // prev sub's buffer reads complete

        const __half* Qg = g_q + base + (size_t)qt * 128 * 64;

        // prologue: group0 = Q + pair0; group1 = pair1 (if any)
#pragma unroll
        for (int i = 0; i < 4; i++)
            CPA16(QPb + (r8 + 32 * i) * 144 + c8 * 16, Qg + (size_t)(r8 + 32 * i) * 64 + c8 * 8);
        KV2_ISSUE(0, 0);
        if (qt >= 1) { KV2_ISSUE(1, 1); CP_WAIT1(); } else { CP_WAIT0(); }
        __syncthreads();

        unsigned qf[4][4];
#pragma unroll
        for (int g = 0; g < 4; g++)
            LDSM4(qf[g][0], qf[g][1], qf[g][2], qf[g][3], aQ + g * 32);

        float m0 = -1e30f, m1 = -1e30f, l0 = 0.f, l1 = 0.f;
        float oacc[8][4];
#pragma unroll
        for (int i = 0; i < 8; i++)
#pragma unroll
            for (int q = 0; q < 4; q++) oacc[i][q] = 0.f;

        for (int p = 0; p <= qt; p++) {
            const int buf = p & 1;

#pragma unroll
            for (int half = 0; half < 2; half++) {
                const uint32_t Kbase = Kb0 + buf * 18432 + half * 9216;
                const uint32_t Vbase = Vb0 + buf * 18432 + half * 9216;
                const int kt = 2 * p + half;
                const int off = kt * 64 - qt * 128;
                const int lim = min(8, max(0, ((16 * w + 15 - off) >> 3) + 1));

                if (lim > 0) {
                    float s[8][4];
#pragma unroll
                    for (int nt = 0; nt < 8; nt++) {
                        s[nt][0] = 0.f; s[nt][1] = 0.f; s[nt][2] = 0.f; s[nt][3] = 0.f;
                    }
                    if (off < 0) {
#pragma unroll
                        for (int g = 0; g < 4; g++) {
                            unsigned bb[8][2];
#pragma unroll
                            for (int ntp = 0; ntp < 4; ntp++)
                                LDSM4(bb[2 * ntp][0], bb[2 * ntp][1], bb[2 * ntp + 1][0], bb[2 * ntp + 1][1],
                                      Kbase + aK + ntp * 2304 + g * 32);
#pragma unroll
                            for (int nt = 0; nt < 8; nt++)
                                mma16(s[nt], qf[g], bb[nt]);
                        }
                    } else {
#pragma unroll
                        for (int g = 0; g < 4; g++) {
                            unsigned bb[8][2];
#pragma unroll
                            for (int ntp = 0; ntp < 4; ntp++)
                                if (2 * ntp < lim)
                                    LDSM4(bb[2 * ntp][0], bb[2 * ntp][1], bb[2 * ntp + 1][0], bb[2 * ntp + 1][1],
                                          Kbase + aK + ntp * 2304 + g * 32);
#pragma unroll
                            for (int nt = 0; nt < 8; nt++)
                                if (nt < lim)
                                    mma16(s[nt], qf[g], bb[nt]);
                        }
#pragma unroll
                        for (int nt = 0; nt < 8; nt++) {
                            if (nt >= lim) {
                                s[nt][0] = s[nt][1] = s[nt][2] = s[nt][3] = -1e30f;
                            } else {
                                int c0 = off + nt * 8 + 2 * lc;
                                if (c0 > row0)     s[nt][0] = -1e30f;
                                if (c0 + 1 > row0) s[nt][1] = -1e30f;
                                if (c0 > row1)     s[nt][2] = -1e30f;
                                if (c0 + 1 > row1) s[nt][3] = -1e30f;
                            }
                        }
                    }

                    float mx0 = -1e30f, mx1 = -1e30f;
#pragma unroll
                    for (int nt = 0; nt < 8; nt++) {
                        mx0 = fmaxf(mx0, fmaxf(s[nt][0], s[nt][1]));
                        mx1 = fmaxf(mx1, fmaxf(s[nt][2], s[nt][3]));
                    }
                    mx0 = fmaxf(mx0, __shfl_xor_sync(0xffffffffu, mx0, 1));
                    mx0 = fmaxf(mx0, __shfl_xor_sync(0xffffffffu, mx0, 2));
                    mx1 = fmaxf(mx1, __shfl_xor_sync(0xffffffffu, mx1, 1));
                    mx1 = fmaxf(mx1, __shfl_xor_sync(0xffffffffu, mx1, 2));
                    float m0n = fmaxf(m0, mx0), m1n = fmaxf(m1, mx1);

                    bool changed = (m0n != m0) || (m1n != m1);
                    if (__any_sync(0xffffffffu, changed)) {
                        float a0 = ex2(m0 - m0n), a1 = ex2(m1 - m1n);
                        m0 = m0n; m1 = m1n;
                        l0 *= a0; l1 *= a1;
#pragma unroll
                        for (int nt = 0; nt < 8; nt++) {
                            oacc[nt][0] *= a0; oacc[nt][1] *= a0;
                            oacc[nt][2] *= a1; oacc[nt][3] *= a1;
                        }
                    }

                    unsigned pf[4][4];
#pragma unroll
                    for (int nt = 0; nt < 8; nt++) {
                        unsigned plo = ex2h2(f2h2(s[nt][0] - m0n, s[nt][1] - m0n));
                        unsigned phi = ex2h2(f2h2(s[nt][2] - m1n, s[nt][3] - m1n));
                        if ((nt & 1) == 0) {
                            pf[nt >> 1][0] = plo;
                            pf[nt >> 1][1] = phi;
                        } else {
                            pf[nt >> 1][2] = plo;
                            pf[nt >> 1][3] = phi;
                        }
                    }

                    float lacc[4] = {0.f, 0.f, 0.f, 0.f};
#pragma unroll
                    for (int g = 0; g < 4; g++) {
                        if (off < 0 || 2 * g < lim) {
                            mma16(lacc, pf[g], onesb);
                            unsigned bb[8][2];
#pragma unroll
                            for (int ntp = 0; ntp < 4; ntp++)
                                LDSM4T(bb[2 * ntp][0], bb[2 * ntp][1], bb[2 * ntp + 1][0], bb[2 * ntp + 1][1],
                                       Vbase + aV + g * 2304 + ntp * 32);
#pragma unroll
                            for (int nt = 0; nt < 8; nt++)
                                mma16(oacc[nt], pf[g], bb[nt]);
                        }
                    }
                    l0 += lacc[0];
                    l1 += lacc[2];
                }
            }

            if (p < qt) {
                CP_WAIT0();
                __syncthreads();
                if (p + 2 <= qt) KV2_ISSUE(p + 2, buf);
            }
        }

        // finalize -> half g_o
        float li0 = 1.f / l0, li1 = 1.f / l1;
        __half* Og = g_o + base + (size_t)qt * 128 * 64;
#pragma unroll
        for (int nt = 0; nt < 8; nt++) {
            int c = nt * 8 + 2 * lc;
            *(unsigned*)(Og + (size_t)row0 * 64 + c) = f2h2(oacc[nt][0] * li0, oacc[nt][1] * li0);
            *(unsigned*)(Og + (size_t)row1 * 64 + c) = f2h2(oacc[nt][2] * li1, oacc[nt][3] * li1);
        }
    }
}

// ---------------------------------------------------------------------------
// Kernel 3: proj GEMM fp16. Block 128m x 128n, BK=32, warp 64x32, K=512.
// 3-stage cp.async pipeline; ldmatrix frags; transpose epilogue.
// (round-13 proven version: 22.2us)
// ---------------------------------------------------------------------------
__global__ void __launch_bounds__(256, 2) proj_gemm_kernel(
    const float* __restrict__ pb, float* __restrict__ out)
{
    extern __shared__ char smem[];
    const uint32_t sb = smem_u32(smem);
    const uint32_t Ab0 = sb;             // 3 x 128*80 = 30720
    const uint32_t Bb0 = sb + 30720;     // 3 x 128*80 = 30720

    const int b  = blockIdx.z;
    const int mT = blockIdx.x * 128;
    const int nT = blockIdx.y * 128;
    const int t = threadIdx.x, lane = t & 31, warp = t >> 5;
    const int wm = (warp & 1) * 64;
    const int wn = (warp >> 1) * 32;
    const int lr = lane >> 2, lc = lane & 3;
    const int l7 = lane & 7, l8 = (lane >> 3) & 1, l16 = lane >> 4;

    const __half* ob = g_o + (size_t)b * (NHEAD * NTOK * 64);

    float acc[4][4][4];
#pragma unroll
    for (int i = 0; i < 4; i++)
#pragma unroll
        for (int j = 0; j < 4; j++)
#pragma unroll
            for (int q = 0; q < 4; q++) acc[i][j][q] = 0.f;

    const int a_r = t >> 1, a_c = t & 1;
#define PROJ_ISSUE(kk, buf) do { \
    int head = (kk) >> 6, d0 = (kk) & 63; \
    const __half* src = ob + (size_t)head * (NTOK * 64); \
    uint32_t Ad = Ab0 + (buf) * 10240, Bd = Bb0 + (buf) * 10240; \
    _Pragma("unroll") \
    for (int i = 0; i < 2; i++) \
        CPA16(Ad + a_r * 80 + (a_c * 2 + i) * 16, \
              src + (size_t)(mT + a_r) * 64 + d0 + (a_c * 2 + i) * 8); \
    _Pragma("unroll") \
    for (int i = 0; i < 2; i++) \
        CPA16(Bd + a_r * 80 + (a_c * 2 + i) * 16, \
              g_pw + (size_t)(nT + a_r) * 512 + (kk) + (a_c * 2 + i) * 8); \
    CP_COMMIT(); } while (0)

    const uint32_t aAl = (uint32_t)((wm + l7 + 8 * l8) * 80 + 16 * l16);
    const uint32_t aBl = (uint32_t)((wn + l7 + 8 * l16) * 80 + 16 * l8);

    PROJ_ISSUE(0, 0);
    PROJ_ISSUE(32, 1);

#pragma unroll
    for (int it = 0; it < 16; it++) {
        const int buf = it % 3;
        CP_WAIT1();
        __syncthreads();
        if (it < 14) PROJ_ISSUE((it + 2) * 32, (it + 2) % 3); else CP_COMMIT();
        const uint32_t Ac = Ab0 + buf * 10240 + aAl;
        const uint32_t Bc = Bb0 + buf * 10240 + aBl;
#pragma unroll
        for (int kg = 0; kg < 2; kg++) {
            unsigned a[4][4], bb[4][2];
#pragma unroll
            for (int mi = 0; mi < 4; mi++)
                LDSM4(a[mi][0], a[mi][1], a[mi][2], a[mi][3],
                      Ac + mi * 1280 + kg * 32);
#pragma unroll
            for (int ntp = 0; ntp < 2; ntp++)
                LDSM4(bb[2 * ntp][0], bb[2 * ntp][1], bb[2 * ntp + 1][0], bb[2 * ntp + 1][1],
                      Bc + ntp * 1280 + kg * 32);
#pragma unroll
            for (int mi = 0; mi < 4; mi++)
#pragma unroll
                for (int ni = 0; ni < 4; ni++)
                    mma16(acc[mi][ni], a[mi], bb[ni]);
        }
    }
    __syncthreads();

    // transpose epilogue through smem: Cs[n][m] ld132 (float)
    float* Cs = (float*)smem;
#pragma unroll
    for (int ni = 0; ni < 4; ni++) {
        int n = wn + ni * 8 + 2 * lc;
#pragma unroll
        for (int mi = 0; mi < 4; mi++) {
            int m = wm + mi * 16 + lr;
            Cs[n * 132 + m]           = acc[mi][ni][0];
            Cs[(n + 1) * 132 + m]     = acc[mi][ni][1];
            Cs[n * 132 + m + 8]       = acc[mi][ni][2];
            Cs[(n + 1) * 132 + m + 8] = acc[mi][ni][3];
        }
    }
    __syncthreads();

#pragma unroll
    for (int i = 0; i < 16; i++) {
        int idx = t + i * 256;
        int n = idx >> 5, mq = (idx & 31) * 4;
        float bi = pb[nT + n];
        const float* src = &Cs[n * 132 + mq];
        float4 v;
        v.x = src[0] + bi; v.y = src[1] + bi; v.z = src[2] + bi; v.w = src[3] + bi;
        *(float4*)(out + (size_t)(b * 256 + nT + n) * NTOK + mT + mq) = v;
    }
}

// ---------------------------------------------------------------------------
extern "C" void kernel_launch(void* const* d_in, const int* in_sizes, int n_in,
                              void* d_out, int out_size)
{
    const float* x      = (const float*)d_in[0];
    const float* qkv_w  = (const float*)d_in[1];
    const float* qkv_b  = (const float*)d_in[2];
    const float* proj_w = (const float*)d_in[3];
    const float* proj_b = (const float*)d_in[4];
    float* out = (float*)d_out;

    const int qkv_smem  = 75776;
    const int attn_smem = 92160;
    const int proj_smem = 128 * 132 * 4;   // 67584 (epilogue dominates)
    cudaFuncSetAttribute(qkv_gemm_kernel, cudaFuncAttributeMaxDynamicSharedMemorySize, qkv_smem);
    cudaFuncSetAttribute(attn_kernel, cudaFuncAttributeMaxDynamicSharedMemorySize, attn_smem);
    cudaFuncSetAttribute(proj_gemm_kernel, cudaFuncAttributeMaxDynamicSharedMemorySize, proj_smem);

    cvt_kernel<<<(X_F4 + W_F4 + PW_F4) / 256, 256>>>(x, qkv_w, proj_w);
    qkv_gemm_kernel<<<dim3(8, 12, BATCH), 256, qkv_smem>>>(qkv_b);
    attn_kernel<<<dim3(4, NHEAD, BATCH), 256, attn_smem>>>();
    proj_gemm_kernel<<<dim3(8, 2, BATCH), 256, proj_smem>>>(proj_b, out);
}